// round 14
// baseline (speedup 1.0000x reference)
#include <cuda_runtime.h>
#include <cuda_fp16.h>
#include <cstdint>

// ---------------- problem constants ----------------
#define NN    50000
#define EE    1600000
#define RR    8
#define NSEG  (NN*RR)        // 400000
#define DH    128
#define KDIM  1152           // 8*128 relation blocks + 128 root (self) block
#define KRED  1024           // relation blocks only (self read direct from feat)
#define GG    64
#define NCLS  10
#define CAP   64             // bucket capacity per (node,relation); P(deg>64)≈0

#define BM    128
#define BK    64
#define NCHUNK (KDIM/BK)     // 18  (chunks 16,17 = self block from feat)

// fp16 smem tiles
#define A_PADH 72                         // halves per A row (144 B)
#define A_TILE_B (BM * A_PADH * 2)        // 18432
#define B_ROWH 272                        // halves per interleaved B k-pair row
#define B_TILE_B (32 * B_ROWH * 2)        // 17408
#define SMEM_GEMM_BYTES (2 * (A_TILE_B + B_TILE_B))   // 71680

#define KP_ROWS (KDIM / 2)                // 576 k-pair rows total
#define WELEMS  (KP_ROWS * B_ROWH)        // 156672

// ---------------- device scratch ----------------
__device__ __align__(16) int g_cnt[NSEG];        // per-segment edge count
__device__ int    g_eidx[(size_t)NSEG * CAP];    // bucketed neighbor lists (102.4 MB)
__device__ __half g_Z[(size_t)NN * KRED];        // 102.4 MB
__device__ __half g_X16[(size_t)NN * DH];
__device__ __half g_H16[(size_t)NN * DH];
__device__ __half g_W1i[WELEMS];
__device__ __half g_W2i[WELEMS];
__device__ float  g_gsum[GG * DH];
__device__ int    g_gcnt[GG];

// ---------------- helpers ----------------
__device__ __forceinline__ uint32_t smem_to_u32(const void* p) {
    uint32_t a;
    asm("{ .reg .u64 t; cvta.to.shared.u64 t, %1; cvt.u32.u64 %0, t; }" : "=r"(a) : "l"(p));
    return a;
}
__device__ __forceinline__ void cp_async16(uint32_t dst, const void* src, uint32_t src_sz) {
    asm volatile("cp.async.cg.shared.global [%0], [%1], 16, %2;"
                 :: "r"(dst), "l"(src), "r"(src_sz));
}
#define CP_COMMIT() asm volatile("cp.async.commit_group;" ::: "memory")
#define CP_WAIT(n)  asm volatile("cp.async.wait_group %0;" :: "n"(n) : "memory")

__device__ __forceinline__ void mma_f16(float* c, const uint32_t* a,
                                        uint32_t b0, uint32_t b1) {
    asm volatile(
        "mma.sync.aligned.m16n8k16.row.col.f32.f16.f16.f32 "
        "{%0,%1,%2,%3}, {%4,%5,%6,%7}, {%8,%9}, {%0,%1,%2,%3};"
        : "+f"(c[0]), "+f"(c[1]), "+f"(c[2]), "+f"(c[3])
        : "r"(a[0]), "r"(a[1]), "r"(a[2]), "r"(a[3]), "r"(b0), "r"(b1));
}

// ---------------- prep: zero + weight interleave + x->fp16 --------------------
__global__ void __launch_bounds__(256) k_prep(const float* __restrict__ x,
                                              const float* __restrict__ W1,
                                              const float* __restrict__ root1,
                                              const float* __restrict__ W2,
                                              const float* __restrict__ root2) {
    int i = blockIdx.x * blockDim.x + threadIdx.x;       // up to NN*32 = 1.6M
    if (i < NSEG)    g_cnt[i] = 0;
    if (i < GG * DH) g_gsum[i] = 0.f;
    if (i < GG)      g_gcnt[i] = 0;
    if (i < WELEMS) {
        int row = i / B_ROWH;
        int j = i % B_ROWH;
        float v1 = 0.f, v2 = 0.f;
        if (j < 256) {
            int n = j >> 1, par = j & 1;
            int k = 2 * row + par;
            if (k < RR * DH) {
                v1 = W1[(size_t)k * DH + n];
                v2 = W2[(size_t)k * DH + n];
            } else {
                v1 = root1[(size_t)(k - RR * DH) * DH + n];
                v2 = root2[(size_t)(k - RR * DH) * DH + n];
            }
        }
        g_W1i[i] = __float2half(v1);
        g_W2i[i] = __float2half(v2);
    }
    if (i < NN * 32) {
        float4 v = *(const float4*)(x + (size_t)i * 4);
        __half2 h0 = __float22half2_rn(make_float2(v.x, v.y));
        __half2 h1 = __float22half2_rn(make_float2(v.z, v.w));
        uint2 u;
        u.x = *(uint32_t*)&h0;
        u.y = *(uint32_t*)&h1;
        *(uint2*)(g_X16 + (size_t)i * 4) = u;
    }
}

// ---------------- direct bucketed fill: 4 edges/thread + graph count ----------
__global__ void k_fill_direct(const int* __restrict__ src, const int* __restrict__ dst,
                              const int* __restrict__ typ, const int* __restrict__ batch) {
    int t = blockIdx.x * blockDim.x + threadIdx.x;
    if (t < EE / 4) {
        int4 s = *(const int4*)(src + 4 * t);
        int4 d = *(const int4*)(dst + 4 * t);
        int4 y = *(const int4*)(typ + 4 * t);
        int seg0 = d.x * RR + y.x;
        int seg1 = d.y * RR + y.y;
        int seg2 = d.z * RR + y.z;
        int seg3 = d.w * RR + y.w;
        int p0 = atomicAdd(&g_cnt[seg0], 1);
        int p1 = atomicAdd(&g_cnt[seg1], 1);
        int p2 = atomicAdd(&g_cnt[seg2], 1);
        int p3 = atomicAdd(&g_cnt[seg3], 1);
        if (p0 < CAP) g_eidx[(size_t)seg0 * CAP + p0] = s.x;
        if (p1 < CAP) g_eidx[(size_t)seg1 * CAP + p1] = s.y;
        if (p2 < CAP) g_eidx[(size_t)seg2 * CAP + p2] = s.z;
        if (p3 < CAP) g_eidx[(size_t)seg3 * CAP + p3] = s.w;
    }
    if (t < NN) atomicAdd(&g_gcnt[batch[t]], 1);
}

// ---------------- aggregation: 2 warps per node, 4 relations each --------------
__global__ void __launch_bounds__(256) k_aggregate_h(const __half* __restrict__ feat) {
    int w = (blockIdx.x * blockDim.x + threadIdx.x) >> 5;
    int lane = threadIdx.x & 31;
    if (w >= NN * 2) return;
    const int node = w >> 1;
    const int rbase = (w & 1) * 4;                 // relations [rbase, rbase+4)
    __half* zrow = g_Z + (size_t)node * KRED + rbase * DH;
    const int co = lane * 4;   // 4 halves per lane

    const int base = node * RR + rbase;            // base % 4 == 0 -> 16B aligned
    int4 cnts4 = *(const int4*)(g_cnt + base);
    int cnts[4] = {cnts4.x, cnts4.y, cnts4.z, cnts4.w};

#pragma unroll
    for (int r = 0; r < 4; r++) {
        const int e = min(cnts[r], CAP);
        const int* lst = g_eidx + (size_t)(base + r) * CAP;
        float4 acc0 = make_float4(0.f, 0.f, 0.f, 0.f);
        float4 acc1 = make_float4(0.f, 0.f, 0.f, 0.f);
        int i = 0;
        for (; i + 4 <= e; i += 4) {
            uint2 u0 = *(const uint2*)(feat + (size_t)lst[i] * DH + co);
            uint2 u1 = *(const uint2*)(feat + (size_t)lst[i + 1] * DH + co);
            uint2 u2 = *(const uint2*)(feat + (size_t)lst[i + 2] * DH + co);
            uint2 u3 = *(const uint2*)(feat + (size_t)lst[i + 3] * DH + co);
            float2 a0 = __half22float2(*(__half2*)&u0.x);
            float2 b0 = __half22float2(*(__half2*)&u0.y);
            float2 a1 = __half22float2(*(__half2*)&u1.x);
            float2 b1 = __half22float2(*(__half2*)&u1.y);
            float2 a2 = __half22float2(*(__half2*)&u2.x);
            float2 b2 = __half22float2(*(__half2*)&u2.y);
            float2 a3 = __half22float2(*(__half2*)&u3.x);
            float2 b3 = __half22float2(*(__half2*)&u3.y);
            acc0.x += a0.x + a1.x; acc0.y += a0.y + a1.y;
            acc0.z += b0.x + b1.x; acc0.w += b0.y + b1.y;
            acc1.x += a2.x + a3.x; acc1.y += a2.y + a3.y;
            acc1.z += b2.x + b3.x; acc1.w += b2.y + b3.y;
        }
        for (; i < e; i++) {
            uint2 u0 = *(const uint2*)(feat + (size_t)lst[i] * DH + co);
            float2 a = __half22float2(*(__half2*)&u0.x);
            float2 b = __half22float2(*(__half2*)&u0.y);
            acc0.x += a.x; acc0.y += a.y; acc0.z += b.x; acc0.w += b.y;
        }
        float inv = (e > 0) ? 1.f / (float)e : 0.f;
        float2 m0 = make_float2((acc0.x + acc1.x) * inv, (acc0.y + acc1.y) * inv);
        float2 m1 = make_float2((acc0.z + acc1.z) * inv, (acc0.w + acc1.w) * inv);
        __half2 h0 = __float22half2_rn(m0);
        __half2 h1 = __float22half2_rn(m1);
        uint2 u;
        u.x = *(uint32_t*)&h0;
        u.y = *(uint32_t*)&h1;
        *(uint2*)(zrow + r * DH + co) = u;
    }
}

// ---------------- fp16 mma GEMM + fused epilogue (BK=64, R9 pipeline) ----------
// A chunks 0..15 from Z (KRED stride); chunks 16,17 = self features from feat.
// mode 0: C16 = relu(...); mode 1: pool into g_gsum.
__global__ void __launch_bounds__(256, 2)
k_gemm_h(const __half* __restrict__ A, const __half* __restrict__ feat,
         const __half* __restrict__ Bi, const float* __restrict__ bias,
         __half* __restrict__ C16, const int* __restrict__ batch, int M, int mode) {
    extern __shared__ __align__(16) char smem[];
    const uint32_t smem_u32 = smem_to_u32(smem);
    const int tid = threadIdx.x;
    const int wid = tid >> 5, lane = tid & 31;
    const int warp_m = wid & 3, warp_n = wid >> 2;
    const int g = lane >> 2, tig = lane & 3;
    const int bm = blockIdx.x * BM;

    const uint32_t aOff[2] = {0u, (uint32_t)A_TILE_B};
    const uint32_t bOff[2] = {(uint32_t)(2 * A_TILE_B), (uint32_t)(2 * A_TILE_B + B_TILE_B)};

    float acc[2][8][4];
#pragma unroll
    for (int i = 0; i < 2; i++)
#pragma unroll
        for (int j = 0; j < 8; j++)
#pragma unroll
            for (int q = 0; q < 4; q++) acc[i][j][q] = 0.f;

    auto load_tile = [&](int c, int buf) {
        // A: 128 rows x 64 halves (128 B/row) -> 1024 16B chunks
#pragma unroll
        for (int it = 0; it < 4; it++) {
            int idx = tid + it * 256;          // 0..1023
            int row = idx >> 3;
            int q = idx & 7;
            int gm = bm + row;
            uint32_t d = smem_u32 + aOff[buf] + row * (A_PADH * 2) + q * 16;
            const __half* srcp = (c < 16)
                ? A + (size_t)gm * KRED + c * BK + q * 8
                : feat + (size_t)gm * DH + (c - 16) * BK + q * 8;
            cp_async16(d, srcp, (gm < M) ? 16u : 0u);
        }
        // B: 32 kp rows x 272 halves = 1088 16B chunks
        const __half* Bb = Bi + (size_t)c * 32 * B_ROWH;
#pragma unroll
        for (int it = 0; it < 5; it++) {
            int idx = tid + it * 256;
            if (idx < 1088)
                cp_async16(smem_u32 + bOff[buf] + idx * 16, Bb + idx * 8, 16u);
        }
    };

    load_tile(0, 0);
    CP_COMMIT();

    const int mbase = warp_m * 32;
    const int nbase = warp_n * 64;

    for (int c = 0; c < NCHUNK; c++) {
        const int buf = c & 1;
        if (c + 1 < NCHUNK) {
            load_tile(c + 1, buf ^ 1);
            CP_COMMIT();
            CP_WAIT(1);
        } else {
            CP_WAIT(0);
        }
        __syncthreads();

        const uint32_t* As = (const uint32_t*)(smem + aOff[buf]);   // row stride 36 words
        const uint32_t* Bs = (const uint32_t*)(smem + bOff[buf]);   // kp stride 136 words

#pragma unroll
        for (int s = 0; s < 4; s++) {           // four k16 steps per BK=64
            const int kw = s * 8;
            uint32_t a[2][4];
#pragma unroll
            for (int mt = 0; mt < 2; mt++) {
                int r0 = mbase + mt * 16 + g;
                a[mt][0] = As[r0 * 36 + kw + tig];
                a[mt][1] = As[(r0 + 8) * 36 + kw + tig];
                a[mt][2] = As[r0 * 36 + kw + tig + 4];
                a[mt][3] = As[(r0 + 8) * 36 + kw + tig + 4];
            }
#pragma unroll
            for (int nt = 0; nt < 8; nt++) {
                int n = nbase + nt * 8 + g;
                uint32_t b0 = Bs[(kw + tig) * 136 + n];
                uint32_t b1 = Bs[(kw + tig + 4) * 136 + n];
                mma_f16(acc[0][nt], a[0], b0, b1);
                mma_f16(acc[1][nt], a[1], b0, b1);
            }
        }
        __syncthreads();
    }

    // ---- epilogue ----
    if (mode == 0) {
#pragma unroll
        for (int nt = 0; nt < 8; nt++) {
            int col = nbase + nt * 8 + tig * 2;
            float b0 = __ldg(bias + col);
            float b1 = __ldg(bias + col + 1);
#pragma unroll
            for (int mt = 0; mt < 2; mt++) {
#pragma unroll
                for (int h = 0; h < 2; h++) {
                    int gm = bm + mbase + mt * 16 + g + h * 8;
                    if (gm >= M) continue;
                    float v0 = fmaxf(acc[mt][nt][2 * h + 0] + b0, 0.f);
                    float v1 = fmaxf(acc[mt][nt][2 * h + 1] + b1, 0.f);
                    __half2 hh = __float22half2_rn(make_float2(v0, v1));
                    *(__half2*)(C16 + (size_t)gm * DH + col) = hh;
                }
            }
        }
    } else {
        int rows[4], grs[4];
        bool ok[4];
#pragma unroll
        for (int q = 0; q < 4; q++) {
            rows[q] = bm + mbase + (q >> 1) * 16 + g + (q & 1) * 8;
            ok[q] = rows[q] < M;
            grs[q] = ok[q] ? __ldg(batch + rows[q]) : -1;
        }
        bool same = ok[0] & ok[1] & ok[2] & ok[3] &
                    (grs[0] == grs[1]) & (grs[0] == grs[2]) & (grs[0] == grs[3]);
#pragma unroll
        for (int nt = 0; nt < 8; nt++) {
            int col = nbase + nt * 8 + tig * 2;
            float b0 = __ldg(bias + col);
            float b1 = __ldg(bias + col + 1);
            if (same) {
                float s0 = 0.f, s1 = 0.f;
#pragma unroll
                for (int q = 0; q < 4; q++) {
                    int mt = q >> 1, h = q & 1;
                    s0 += fmaxf(acc[mt][nt][2 * h + 0] + b0, 0.f);
                    s1 += fmaxf(acc[mt][nt][2 * h + 1] + b1, 0.f);
                }
                atomicAdd(&g_gsum[grs[0] * DH + col], s0);
                atomicAdd(&g_gsum[grs[0] * DH + col + 1], s1);
            } else {
#pragma unroll
                for (int q = 0; q < 4; q++) {
                    if (!ok[q]) continue;
                    int mt = q >> 1, h = q & 1;
                    float v0 = fmaxf(acc[mt][nt][2 * h + 0] + b0, 0.f);
                    float v1 = fmaxf(acc[mt][nt][2 * h + 1] + b1, 0.f);
                    atomicAdd(&g_gsum[grs[q] * DH + col], v0);
                    atomicAdd(&g_gsum[grs[q] * DH + col + 1], v1);
                }
            }
        }
    }
}

// ---------------- final linear: one block per graph ----------------------------
__global__ void __launch_bounds__(128) k_final(const float* __restrict__ lw,
                                               const float* __restrict__ lb,
                                               float* __restrict__ out) {
    __shared__ float row[DH];
    __shared__ float cls[NCLS][4];
    const int g = blockIdx.x;
    const int t = threadIdx.x;
    const float inv = 1.f / fmaxf((float)g_gcnt[g], 1.f);
    row[t] = g_gsum[g * DH + t] * inv;
    __syncthreads();

    if (t < NCLS * 4) {
        int c = t >> 2, part = t & 3;
        float s = 0.f;
#pragma unroll
        for (int d = part * 32; d < part * 32 + 32; d++)
            s += row[d] * __ldg(lw + d * NCLS + c);
        cls[c][part] = s;
    }
    __syncthreads();
    if (t < NCLS)
        out[g * NCLS + t] = cls[t][0] + cls[t][1] + cls[t][2] + cls[t][3] + __ldg(lb + t);
}

// ---------------- launch ----------------
extern "C" void kernel_launch(void* const* d_in, const int* in_sizes, int n_in,
                              void* d_out, int out_size) {
    const float* x     = (const float*)d_in[0];
    const int*   ei    = (const int*)d_in[1];     // [2,E]
    const int*   etype = (const int*)d_in[2];
    const int*   batch = (const int*)d_in[3];
    const float* W1    = (const float*)d_in[4];
    const float* root1 = (const float*)d_in[5];
    const float* b1    = (const float*)d_in[6];
    const float* W2    = (const float*)d_in[7];
    const float* root2 = (const float*)d_in[8];
    const float* b2    = (const float*)d_in[9];
    const float* lw    = (const float*)d_in[10];
    const float* lb    = (const float*)d_in[11];
    float* out = (float*)d_out;

    const int* src = ei;
    const int* dst = ei + EE;

    __half *Z, *X16, *H16, *W1i, *W2i;
    cudaGetSymbolAddress((void**)&Z,   g_Z);
    cudaGetSymbolAddress((void**)&X16, g_X16);
    cudaGetSymbolAddress((void**)&H16, g_H16);
    cudaGetSymbolAddress((void**)&W1i, g_W1i);
    cudaGetSymbolAddress((void**)&W2i, g_W2i);

    cudaFuncSetAttribute(k_gemm_h, cudaFuncAttributeMaxDynamicSharedMemorySize,
                         SMEM_GEMM_BYTES);

    const int TB = 256;

    // prep (zero/convert/interleave)
    k_prep<<<(NN * 32 + TB - 1) / TB, TB>>>(x, W1, root1, W2, root2);
    // direct bucketed adjacency fill (replaces count/scan/scan/fill)
    k_fill_direct<<<(EE / 4 + TB - 1) / TB, TB>>>(src, dst, etype, batch);

    const int aggBlocks = (NN * 2 * 32 + TB - 1) / TB;   // 2 warps per node
    const int gemmBlocks = (NN + BM - 1) / BM;           // 391

    // layer 1
    k_aggregate_h<<<aggBlocks, TB>>>(X16);
    k_gemm_h<<<gemmBlocks, TB, SMEM_GEMM_BYTES>>>(Z, X16, W1i, b1, H16, batch, NN, 0);
    // layer 2 (fused pool epilogue)
    k_aggregate_h<<<aggBlocks, TB>>>(H16);
    k_gemm_h<<<gemmBlocks, TB, SMEM_GEMM_BYTES>>>(Z, H16, W2i, b2, nullptr, batch, NN, 1);

    // classify
    k_final<<<GG, 128>>>(lw, lb, out);
}

// round 15
// speedup vs baseline: 1.1210x; 1.1210x over previous
#include <cuda_runtime.h>
#include <cuda_fp16.h>
#include <cstdint>

// ---------------- problem constants ----------------
#define NN    50000
#define EE    1600000
#define RR    8
#define NSEG  (NN*RR)        // 400000
#define DH    128
#define KDIM  1152           // 8*128 relation blocks + 128 root (self) block
#define KRED  1024           // relation blocks only (self read direct from feat)
#define GG    64
#define NCLS  10

#define BM    128
#define BK    64
#define NCHUNK (KDIM/BK)     // 18  (chunks 16,17 = self block from feat)

// fp16 smem tiles, 3-stage pipeline
#define A_PADH 72                         // halves per A row (144 B)
#define A_TILE_B (BM * A_PADH * 2)        // 18432
#define B_ROWH 272                        // halves per interleaved B k-pair row
#define B_TILE_B (32 * B_ROWH * 2)        // 17408
#define NSTAGE 3
#define SMEM_GEMM_BYTES (NSTAGE * (A_TILE_B + B_TILE_B))   // 107520

#define KP_ROWS (KDIM / 2)                // 576 k-pair rows total
#define WELEMS  (KP_ROWS * B_ROWH)        // 156672

// ---------------- device scratch ----------------
__device__ int    g_deg[NSEG];
__device__ __align__(16) int g_offs[NSEG + 4];   // 16B-aligned for int4 loads
__device__ int    g_cursor[NSEG];
__device__ int    g_bsum[512];
__device__ int    g_eidx[EE];
__device__ __half g_Z[(size_t)NN * KRED];        // 102.4 MB
__device__ __half g_X16[(size_t)NN * DH];
__device__ __half g_H16[(size_t)NN * DH];
__device__ __half g_W1i[WELEMS];
__device__ __half g_W2i[WELEMS];
__device__ float  g_gsum[GG * DH];
__device__ int    g_gcnt[GG];

// ---------------- helpers ----------------
__device__ __forceinline__ uint32_t smem_to_u32(const void* p) {
    uint32_t a;
    asm("{ .reg .u64 t; cvta.to.shared.u64 t, %1; cvt.u32.u64 %0, t; }" : "=r"(a) : "l"(p));
    return a;
}
__device__ __forceinline__ void cp_async16(uint32_t dst, const void* src, uint32_t src_sz) {
    asm volatile("cp.async.cg.shared.global [%0], [%1], 16, %2;"
                 :: "r"(dst), "l"(src), "r"(src_sz));
}
#define CP_COMMIT() asm volatile("cp.async.commit_group;" ::: "memory")
#define CP_WAIT(n)  asm volatile("cp.async.wait_group %0;" :: "n"(n) : "memory")

__device__ __forceinline__ void mma_f16(float* c, const uint32_t* a,
                                        uint32_t b0, uint32_t b1) {
    asm volatile(
        "mma.sync.aligned.m16n8k16.row.col.f32.f16.f16.f32 "
        "{%0,%1,%2,%3}, {%4,%5,%6,%7}, {%8,%9}, {%0,%1,%2,%3};"
        : "+f"(c[0]), "+f"(c[1]), "+f"(c[2]), "+f"(c[3])
        : "r"(a[0]), "r"(a[1]), "r"(a[2]), "r"(a[3]), "r"(b0), "r"(b1));
}

// ---------------- prep: zero + weight interleave + x->fp16 --------------------
__global__ void __launch_bounds__(256) k_prep(const float* __restrict__ x,
                                              const float* __restrict__ W1,
                                              const float* __restrict__ root1,
                                              const float* __restrict__ W2,
                                              const float* __restrict__ root2) {
    int i = blockIdx.x * blockDim.x + threadIdx.x;       // up to NN*32 = 1.6M
    if (i < NSEG)    g_deg[i] = 0;
    if (i < GG * DH) g_gsum[i] = 0.f;
    if (i < GG)      g_gcnt[i] = 0;
    if (i < WELEMS) {
        int row = i / B_ROWH;
        int j = i % B_ROWH;
        float v1 = 0.f, v2 = 0.f;
        if (j < 256) {
            int n = j >> 1, par = j & 1;
            int k = 2 * row + par;
            if (k < RR * DH) {
                v1 = W1[(size_t)k * DH + n];
                v2 = W2[(size_t)k * DH + n];
            } else {
                v1 = root1[(size_t)(k - RR * DH) * DH + n];
                v2 = root2[(size_t)(k - RR * DH) * DH + n];
            }
        }
        g_W1i[i] = __float2half(v1);
        g_W2i[i] = __float2half(v2);
    }
    if (i < NN * 32) {
        float4 v = *(const float4*)(x + (size_t)i * 4);
        __half2 h0 = __float22half2_rn(make_float2(v.x, v.y));
        __half2 h1 = __float22half2_rn(make_float2(v.z, v.w));
        uint2 u;
        u.x = *(uint32_t*)&h0;
        u.y = *(uint32_t*)&h1;
        *(uint2*)(g_X16 + (size_t)i * 4) = u;
    }
}

// ---------------- CSR build: 4 edges/thread -----------------------------------
__global__ void k_count(const int* __restrict__ dst, const int* __restrict__ typ,
                        const int* __restrict__ batch) {
    int t = blockIdx.x * blockDim.x + threadIdx.x;
    if (t < EE / 4) {
        int4 d = *(const int4*)(dst + 4 * t);
        int4 y = *(const int4*)(typ + 4 * t);
        atomicAdd(&g_deg[d.x * RR + y.x], 1);
        atomicAdd(&g_deg[d.y * RR + y.y], 1);
        atomicAdd(&g_deg[d.z * RR + y.z], 1);
        atomicAdd(&g_deg[d.w * RR + y.w], 1);
    }
    if (t < NN) atomicAdd(&g_gcnt[batch[t]], 1);
}

// block sums over 1024-element tiles of g_deg
__global__ void __launch_bounds__(1024) k_scan_sums() {
    __shared__ int red[32];
    int i = blockIdx.x * 1024 + threadIdx.x;
    int lane = threadIdx.x & 31, warp = threadIdx.x >> 5;
    int v = (i < NSEG) ? g_deg[i] : 0;
    int s = v;
#pragma unroll
    for (int o = 16; o > 0; o >>= 1) s += __shfl_down_sync(0xFFFFFFFFu, s, o);
    if (lane == 0) red[warp] = s;
    __syncthreads();
    if (threadIdx.x < 32) {
        int r = red[threadIdx.x];
#pragma unroll
        for (int o = 16; o > 0; o >>= 1) r += __shfl_down_sync(0xFFFFFFFFu, r, o);
        if (threadIdx.x == 0) g_bsum[blockIdx.x] = r;
    }
}

// per-block: reduce preceding block sums -> offset; local exclusive scan; write
__global__ void __launch_bounds__(1024) k_scan_apply() {
    __shared__ int red[32];
    __shared__ int s_boff;
    __shared__ int wsum[32];
    const int t = threadIdx.x;
    const int lane = t & 31, warp = t >> 5;
    const int b = blockIdx.x;

    int local = (t < b) ? g_bsum[t] : 0;
#pragma unroll
    for (int o = 16; o > 0; o >>= 1) local += __shfl_down_sync(0xFFFFFFFFu, local, o);
    if (lane == 0) red[warp] = local;
    __syncthreads();
    if (t < 32) {
        int r = red[t];
#pragma unroll
        for (int o = 16; o > 0; o >>= 1) r += __shfl_down_sync(0xFFFFFFFFu, r, o);
        if (t == 0) s_boff = r;
    }
    __syncthreads();
    const int boff = s_boff;

    int i = b * 1024 + t;
    int v = (i < NSEG) ? g_deg[i] : 0;
    int x = v;
#pragma unroll
    for (int o = 1; o < 32; o <<= 1) {
        int y = __shfl_up_sync(0xFFFFFFFFu, x, o);
        if (lane >= o) x += y;
    }
    if (lane == 31) wsum[warp] = x;
    __syncthreads();
    if (t < 32) {
        int y = wsum[t];
        int z = y;
#pragma unroll
        for (int o = 1; o < 32; o <<= 1) {
            int q = __shfl_up_sync(0xFFFFFFFFu, z, o);
            if (t >= o) z += q;
        }
        wsum[t] = z - y;
    }
    __syncthreads();
    if (i < NSEG) {
        int o = x - v + wsum[warp] + boff;
        g_offs[i] = o;
        g_cursor[i] = o;
    }
    if (b == 0 && t == 0) g_offs[NSEG] = EE;
}

__global__ void k_fill(const int* __restrict__ src, const int* __restrict__ dst,
                       const int* __restrict__ typ) {
    int t = blockIdx.x * blockDim.x + threadIdx.x;
    if (t >= EE / 4) return;
    int4 s = *(const int4*)(src + 4 * t);
    int4 d = *(const int4*)(dst + 4 * t);
    int4 y = *(const int4*)(typ + 4 * t);
    int p0 = atomicAdd(&g_cursor[d.x * RR + y.x], 1);
    int p1 = atomicAdd(&g_cursor[d.y * RR + y.y], 1);
    int p2 = atomicAdd(&g_cursor[d.z * RR + y.z], 1);
    int p3 = atomicAdd(&g_cursor[d.w * RR + y.w], 1);
    g_eidx[p0] = s.x;
    g_eidx[p1] = s.y;
    g_eidx[p2] = s.z;
    g_eidx[p3] = s.w;
}

// ---------------- aggregation: 2 warps per node, 4 relations each --------------
__global__ void __launch_bounds__(256) k_aggregate_h(const __half* __restrict__ feat) {
    int w = (blockIdx.x * blockDim.x + threadIdx.x) >> 5;
    int lane = threadIdx.x & 31;
    if (w >= NN * 2) return;
    const int node = w >> 1;
    const int rbase = (w & 1) * 4;                 // relations [rbase, rbase+4)
    __half* zrow = g_Z + (size_t)node * KRED + rbase * DH;
    const int co = lane * 4;   // 4 halves per lane

    const int base = node * RR + rbase;            // base % 4 == 0 -> 16B aligned
    int4 oA = *(const int4*)(g_offs + base);
    int o4 = g_offs[base + 4];
    int offs[5] = {oA.x, oA.y, oA.z, oA.w, o4};

#pragma unroll
    for (int r = 0; r < 4; r++) {
        int s = offs[r];
        int e = offs[r + 1];
        float4 acc0 = make_float4(0.f, 0.f, 0.f, 0.f);
        float4 acc1 = make_float4(0.f, 0.f, 0.f, 0.f);
        int i = s;
        for (; i + 4 <= e; i += 4) {
            uint2 u0 = *(const uint2*)(feat + (size_t)g_eidx[i] * DH + co);
            uint2 u1 = *(const uint2*)(feat + (size_t)g_eidx[i + 1] * DH + co);
            uint2 u2 = *(const uint2*)(feat + (size_t)g_eidx[i + 2] * DH + co);
            uint2 u3 = *(const uint2*)(feat + (size_t)g_eidx[i + 3] * DH + co);
            float2 a0 = __half22float2(*(__half2*)&u0.x);
            float2 b0 = __half22float2(*(__half2*)&u0.y);
            float2 a1 = __half22float2(*(__half2*)&u1.x);
            float2 b1 = __half22float2(*(__half2*)&u1.y);
            float2 a2 = __half22float2(*(__half2*)&u2.x);
            float2 b2 = __half22float2(*(__half2*)&u2.y);
            float2 a3 = __half22float2(*(__half2*)&u3.x);
            float2 b3 = __half22float2(*(__half2*)&u3.y);
            acc0.x += a0.x + a1.x; acc0.y += a0.y + a1.y;
            acc0.z += b0.x + b1.x; acc0.w += b0.y + b1.y;
            acc1.x += a2.x + a3.x; acc1.y += a2.y + a3.y;
            acc1.z += b2.x + b3.x; acc1.w += b2.y + b3.y;
        }
        for (; i < e; i++) {
            uint2 u0 = *(const uint2*)(feat + (size_t)g_eidx[i] * DH + co);
            float2 a = __half22float2(*(__half2*)&u0.x);
            float2 b = __half22float2(*(__half2*)&u0.y);
            acc0.x += a.x; acc0.y += a.y; acc0.z += b.x; acc0.w += b.y;
        }
        float inv = (e > s) ? 1.f / (float)(e - s) : 0.f;
        float2 m0 = make_float2((acc0.x + acc1.x) * inv, (acc0.y + acc1.y) * inv);
        float2 m1 = make_float2((acc0.z + acc1.z) * inv, (acc0.w + acc1.w) * inv);
        __half2 h0 = __float22half2_rn(m0);
        __half2 h1 = __float22half2_rn(m1);
        uint2 u;
        u.x = *(uint32_t*)&h0;
        u.y = *(uint32_t*)&h1;
        *(uint2*)(zrow + r * DH + co) = u;
    }
}

// ---------------- fp16 mma GEMM, 3-stage cp.async pipeline ---------------------
// A chunks 0..15 from Z (KRED stride); chunks 16,17 = self features from feat.
// mode 0: C16 = relu(...); mode 1: pool into g_gsum.
__global__ void __launch_bounds__(256, 2)
k_gemm_h(const __half* __restrict__ A, const __half* __restrict__ feat,
         const __half* __restrict__ Bi, const float* __restrict__ bias,
         __half* __restrict__ C16, const int* __restrict__ batch, int M, int mode) {
    extern __shared__ __align__(16) char smem[];
    const uint32_t smem_u32 = smem_to_u32(smem);
    const int tid = threadIdx.x;
    const int wid = tid >> 5, lane = tid & 31;
    const int warp_m = wid & 3, warp_n = wid >> 2;
    const int g = lane >> 2, tig = lane & 3;
    const int bm = blockIdx.x * BM;

    uint32_t aOff[NSTAGE], bOff[NSTAGE];
#pragma unroll
    for (int s = 0; s < NSTAGE; s++) {
        aOff[s] = s * (A_TILE_B + B_TILE_B);
        bOff[s] = aOff[s] + A_TILE_B;
    }

    float acc[2][8][4];
#pragma unroll
    for (int i = 0; i < 2; i++)
#pragma unroll
        for (int j = 0; j < 8; j++)
#pragma unroll
            for (int q = 0; q < 4; q++) acc[i][j][q] = 0.f;

    auto load_tile = [&](int c, int buf) {
        // A: 128 rows x 64 halves (128 B/row) -> 1024 16B chunks
#pragma unroll
        for (int it = 0; it < 4; it++) {
            int idx = tid + it * 256;          // 0..1023
            int row = idx >> 3;
            int q = idx & 7;
            int gm = bm + row;
            uint32_t d = smem_u32 + aOff[buf] + row * (A_PADH * 2) + q * 16;
            const __half* srcp = (c < 16)
                ? A + (size_t)gm * KRED + c * BK + q * 8
                : feat + (size_t)gm * DH + (c - 16) * BK + q * 8;
            cp_async16(d, srcp, (gm < M) ? 16u : 0u);
        }
        // B: 32 kp rows x 272 halves = 1088 16B chunks
        const __half* Bb = Bi + (size_t)c * 32 * B_ROWH;
#pragma unroll
        for (int it = 0; it < 5; it++) {
            int idx = tid + it * 256;
            if (idx < 1088)
                cp_async16(smem_u32 + bOff[buf] + idx * 16, Bb + idx * 8, 16u);
        }
    };

    load_tile(0, 0);
    CP_COMMIT();
    load_tile(1, 1);
    CP_COMMIT();

    const int mbase = warp_m * 32;
    const int nbase = warp_n * 64;

    for (int c = 0; c < NCHUNK; c++) {
        const int buf = c % NSTAGE;
        if (c + 1 < NCHUNK) CP_WAIT(1); else CP_WAIT(0);   // tile c landed
        __syncthreads();     // all threads done with buf (c-1)%NSTAGE compute
        if (c + 2 < NCHUNK) {
            load_tile(c + 2, (c + 2) % NSTAGE);   // overwrites tile c-1's buffer: safe
            CP_COMMIT();
        }

        const uint32_t* As = (const uint32_t*)(smem + aOff[buf]);   // row stride 36 words
        const uint32_t* Bs = (const uint32_t*)(smem + bOff[buf]);   // kp stride 136 words

#pragma unroll
        for (int s = 0; s < 4; s++) {           // four k16 steps per BK=64
            const int kw = s * 8;
            uint32_t a[2][4];
#pragma unroll
            for (int mt = 0; mt < 2; mt++) {
                int r0 = mbase + mt * 16 + g;
                a[mt][0] = As[r0 * 36 + kw + tig];
                a[mt][1] = As[(r0 + 8) * 36 + kw + tig];
                a[mt][2] = As[r0 * 36 + kw + tig + 4];
                a[mt][3] = As[(r0 + 8) * 36 + kw + tig + 4];
            }
#pragma unroll
            for (int nt = 0; nt < 8; nt++) {
                int n = nbase + nt * 8 + g;
                uint32_t b0 = Bs[(kw + tig) * 136 + n];
                uint32_t b1 = Bs[(kw + tig + 4) * 136 + n];
                mma_f16(acc[0][nt], a[0], b0, b1);
                mma_f16(acc[1][nt], a[1], b0, b1);
            }
        }
    }

    // ---- epilogue ----
    if (mode == 0) {
#pragma unroll
        for (int nt = 0; nt < 8; nt++) {
            int col = nbase + nt * 8 + tig * 2;
            float b0 = __ldg(bias + col);
            float b1 = __ldg(bias + col + 1);
#pragma unroll
            for (int mt = 0; mt < 2; mt++) {
#pragma unroll
                for (int h = 0; h < 2; h++) {
                    int gm = bm + mbase + mt * 16 + g + h * 8;
                    if (gm >= M) continue;
                    float v0 = fmaxf(acc[mt][nt][2 * h + 0] + b0, 0.f);
                    float v1 = fmaxf(acc[mt][nt][2 * h + 1] + b1, 0.f);
                    __half2 hh = __float22half2_rn(make_float2(v0, v1));
                    *(__half2*)(C16 + (size_t)gm * DH + col) = hh;
                }
            }
        }
    } else {
        int rows[4], grs[4];
        bool ok[4];
#pragma unroll
        for (int q = 0; q < 4; q++) {
            rows[q] = bm + mbase + (q >> 1) * 16 + g + (q & 1) * 8;
            ok[q] = rows[q] < M;
            grs[q] = ok[q] ? __ldg(batch + rows[q]) : -1;
        }
        bool same = ok[0] & ok[1] & ok[2] & ok[3] &
                    (grs[0] == grs[1]) & (grs[0] == grs[2]) & (grs[0] == grs[3]);
#pragma unroll
        for (int nt = 0; nt < 8; nt++) {
            int col = nbase + nt * 8 + tig * 2;
            float b0 = __ldg(bias + col);
            float b1 = __ldg(bias + col + 1);
            if (same) {
                float s0 = 0.f, s1 = 0.f;
#pragma unroll
                for (int q = 0; q < 4; q++) {
                    int mt = q >> 1, h = q & 1;
                    s0 += fmaxf(acc[mt][nt][2 * h + 0] + b0, 0.f);
                    s1 += fmaxf(acc[mt][nt][2 * h + 1] + b1, 0.f);
                }
                atomicAdd(&g_gsum[grs[0] * DH + col], s0);
                atomicAdd(&g_gsum[grs[0] * DH + col + 1], s1);
            } else {
#pragma unroll
                for (int q = 0; q < 4; q++) {
                    if (!ok[q]) continue;
                    int mt = q >> 1, h = q & 1;
                    float v0 = fmaxf(acc[mt][nt][2 * h + 0] + b0, 0.f);
                    float v1 = fmaxf(acc[mt][nt][2 * h + 1] + b1, 0.f);
                    atomicAdd(&g_gsum[grs[q] * DH + col], v0);
                    atomicAdd(&g_gsum[grs[q] * DH + col + 1], v1);
                }
            }
        }
    }
}

// ---------------- final linear: one block per graph ----------------------------
__global__ void __launch_bounds__(128) k_final(const float* __restrict__ lw,
                                               const float* __restrict__ lb,
                                               float* __restrict__ out) {
    __shared__ float row[DH];
    __shared__ float cls[NCLS][4];
    const int g = blockIdx.x;
    const int t = threadIdx.x;
    const float inv = 1.f / fmaxf((float)g_gcnt[g], 1.f);
    row[t] = g_gsum[g * DH + t] * inv;
    __syncthreads();

    if (t < NCLS * 4) {
        int c = t >> 2, part = t & 3;
        float s = 0.f;
#pragma unroll
        for (int d = part * 32; d < part * 32 + 32; d++)
            s += row[d] * __ldg(lw + d * NCLS + c);
        cls[c][part] = s;
    }
    __syncthreads();
    if (t < NCLS)
        out[g * NCLS + t] = cls[t][0] + cls[t][1] + cls[t][2] + cls[t][3] + __ldg(lb + t);
}

// ---------------- launch ----------------
extern "C" void kernel_launch(void* const* d_in, const int* in_sizes, int n_in,
                              void* d_out, int out_size) {
    const float* x     = (const float*)d_in[0];
    const int*   ei    = (const int*)d_in[1];     // [2,E]
    const int*   etype = (const int*)d_in[2];
    const int*   batch = (const int*)d_in[3];
    const float* W1    = (const float*)d_in[4];
    const float* root1 = (const float*)d_in[5];
    const float* b1    = (const float*)d_in[6];
    const float* W2    = (const float*)d_in[7];
    const float* root2 = (const float*)d_in[8];
    const float* b2    = (const float*)d_in[9];
    const float* lw    = (const float*)d_in[10];
    const float* lb    = (const float*)d_in[11];
    float* out = (float*)d_out;

    const int* src = ei;
    const int* dst = ei + EE;

    __half *Z, *X16, *H16, *W1i, *W2i;
    cudaGetSymbolAddress((void**)&Z,   g_Z);
    cudaGetSymbolAddress((void**)&X16, g_X16);
    cudaGetSymbolAddress((void**)&H16, g_H16);
    cudaGetSymbolAddress((void**)&W1i, g_W1i);
    cudaGetSymbolAddress((void**)&W2i, g_W2i);

    cudaFuncSetAttribute(k_gemm_h, cudaFuncAttributeMaxDynamicSharedMemorySize,
                         SMEM_GEMM_BYTES);

    const int TB = 256;
    const int scanBlocks = (NSEG + 1023) / 1024;    // 391

    // prep (zero/convert/interleave)
    k_prep<<<(NN * 32 + TB - 1) / TB, TB>>>(x, W1, root1, W2, root2);
    // CSR build (4 edges/thread)
    k_count<<<(EE / 4 + TB - 1) / TB, TB>>>(dst, etype, batch);
    k_scan_sums<<<scanBlocks, 1024>>>();
    k_scan_apply<<<scanBlocks, 1024>>>();
    k_fill<<<(EE / 4 + TB - 1) / TB, TB>>>(src, dst, etype);

    const int aggBlocks = (NN * 2 * 32 + TB - 1) / TB;   // 2 warps per node
    const int gemmBlocks = (NN + BM - 1) / BM;           // 391

    // layer 1
    k_aggregate_h<<<aggBlocks, TB>>>(X16);
    k_gemm_h<<<gemmBlocks, TB, SMEM_GEMM_BYTES>>>(Z, X16, W1i, b1, H16, batch, NN, 0);
    // layer 2 (fused pool epilogue)
    k_aggregate_h<<<aggBlocks, TB>>>(H16);
    k_gemm_h<<<gemmBlocks, TB, SMEM_GEMM_BYTES>>>(Z, H16, W2i, b2, nullptr, batch, NN, 1);

    // classify
    k_final<<<GG, 128>>>(lw, lb, out);
}

// round 16
// speedup vs baseline: 1.1304x; 1.0083x over previous
#include <cuda_runtime.h>
#include <cuda_fp16.h>
#include <cstdint>

// ---------------- problem constants ----------------
#define NN    50000
#define EE    1600000
#define RR    8
#define NSEG  (NN*RR)        // 400000
#define DH    128
#define KDIM  1152           // 8*128 relation blocks + 128 root (self) block
#define KRED  1024           // relation blocks only (self read direct from feat)
#define GG    64
#define NCLS  10

#define BM    128
#define BK    64
#define NCHUNK (KDIM/BK)     // 18  (chunks 16,17 = self block from feat)

// fp16 smem tiles
#define A_PADH 72                         // halves per A row (144 B)
#define A_TILE_B (BM * A_PADH * 2)        // 18432
// B paired layout: per chunk: [s:4][n:128][tig:4][h:2] halves = 8192 halves = 16 KB
#define B_TILE_B 16384
#define SMEM_GEMM_BYTES (2 * (A_TILE_B + B_TILE_B))   // 69632

#define WELEMS2 (NCHUNK * 8192)           // 147456 halves per weight matrix

// ---------------- device scratch ----------------
__device__ int    g_deg[NSEG];
__device__ __align__(16) int g_offs[NSEG + 4];   // 16B-aligned for int4 loads
__device__ int    g_cursor[NSEG];
__device__ int    g_bsum[512];
__device__ int    g_eidx[EE];
__device__ __half g_Z[(size_t)NN * KRED];        // 102.4 MB
__device__ __half g_X16[(size_t)NN * DH];
__device__ __half g_H16[(size_t)NN * DH];
__device__ __half g_W1i[WELEMS2];
__device__ __half g_W2i[WELEMS2];
__device__ float  g_gsum[GG * DH];
__device__ int    g_gcnt[GG];

// ---------------- helpers ----------------
__device__ __forceinline__ uint32_t smem_to_u32(const void* p) {
    uint32_t a;
    asm("{ .reg .u64 t; cvta.to.shared.u64 t, %1; cvt.u32.u64 %0, t; }" : "=r"(a) : "l"(p));
    return a;
}
__device__ __forceinline__ void cp_async16(uint32_t dst, const void* src, uint32_t src_sz) {
    asm volatile("cp.async.cg.shared.global [%0], [%1], 16, %2;"
                 :: "r"(dst), "l"(src), "r"(src_sz));
}
#define CP_COMMIT() asm volatile("cp.async.commit_group;" ::: "memory")
#define CP_WAIT(n)  asm volatile("cp.async.wait_group %0;" :: "n"(n) : "memory")

__device__ __forceinline__ void mma_f16(float* c, const uint32_t* a,
                                        uint32_t b0, uint32_t b1) {
    asm volatile(
        "mma.sync.aligned.m16n8k16.row.col.f32.f16.f16.f32 "
        "{%0,%1,%2,%3}, {%4,%5,%6,%7}, {%8,%9}, {%0,%1,%2,%3};"
        : "+f"(c[0]), "+f"(c[1]), "+f"(c[2]), "+f"(c[3])
        : "r"(a[0]), "r"(a[1]), "r"(a[2]), "r"(a[3]), "r"(b0), "r"(b1));
}

// ---------------- prep: zero + paired weight interleave + x->fp16 -------------
// Weight layout (halves): i -> word w=i>>1, par=i&1;
//   c = w/4096; s = (w%4096)>>10; r2 = w&1023; n = r2>>3; tig = (r2&7)>>1; h = r2&1
//   k-pair kp = c*32 + s*8 + tig + h*4 ; k = 2*kp + par
__global__ void __launch_bounds__(256) k_prep(const float* __restrict__ x,
                                              const float* __restrict__ W1,
                                              const float* __restrict__ root1,
                                              const float* __restrict__ W2,
                                              const float* __restrict__ root2) {
    int i = blockIdx.x * blockDim.x + threadIdx.x;       // up to NN*32 = 1.6M
    if (i < NSEG)    g_deg[i] = 0;
    if (i < GG * DH) g_gsum[i] = 0.f;
    if (i < GG)      g_gcnt[i] = 0;
    if (i < WELEMS2) {
        int w = i >> 1, par = i & 1;
        int c = w >> 12;            // /4096
        int rem = w & 4095;
        int s = rem >> 10;
        int r2 = rem & 1023;
        int n = r2 >> 3;
        int q = r2 & 7;
        int tig = q >> 1, h = q & 1;
        int kp = c * 32 + s * 8 + tig + h * 4;
        int k = 2 * kp + par;
        float v1, v2;
        if (k < RR * DH) {
            v1 = W1[(size_t)k * DH + n];
            v2 = W2[(size_t)k * DH + n];
        } else {
            v1 = root1[(size_t)(k - RR * DH) * DH + n];
            v2 = root2[(size_t)(k - RR * DH) * DH + n];
        }
        g_W1i[i] = __float2half(v1);
        g_W2i[i] = __float2half(v2);
    }
    if (i < NN * 32) {
        float4 v = *(const float4*)(x + (size_t)i * 4);
        __half2 h0 = __float22half2_rn(make_float2(v.x, v.y));
        __half2 h1 = __float22half2_rn(make_float2(v.z, v.w));
        uint2 u;
        u.x = *(uint32_t*)&h0;
        u.y = *(uint32_t*)&h1;
        *(uint2*)(g_X16 + (size_t)i * 4) = u;
    }
}

// ---------------- CSR build: 4 edges/thread -----------------------------------
__global__ void k_count(const int* __restrict__ dst, const int* __restrict__ typ,
                        const int* __restrict__ batch) {
    int t = blockIdx.x * blockDim.x + threadIdx.x;
    if (t < EE / 4) {
        int4 d = *(const int4*)(dst + 4 * t);
        int4 y = *(const int4*)(typ + 4 * t);
        atomicAdd(&g_deg[d.x * RR + y.x], 1);
        atomicAdd(&g_deg[d.y * RR + y.y], 1);
        atomicAdd(&g_deg[d.z * RR + y.z], 1);
        atomicAdd(&g_deg[d.w * RR + y.w], 1);
    }
    if (t < NN) atomicAdd(&g_gcnt[batch[t]], 1);
}

// block sums over 1024-element tiles of g_deg
__global__ void __launch_bounds__(1024) k_scan_sums() {
    __shared__ int red[32];
    int i = blockIdx.x * 1024 + threadIdx.x;
    int lane = threadIdx.x & 31, warp = threadIdx.x >> 5;
    int v = (i < NSEG) ? g_deg[i] : 0;
    int s = v;
#pragma unroll
    for (int o = 16; o > 0; o >>= 1) s += __shfl_down_sync(0xFFFFFFFFu, s, o);
    if (lane == 0) red[warp] = s;
    __syncthreads();
    if (threadIdx.x < 32) {
        int r = red[threadIdx.x];
#pragma unroll
        for (int o = 16; o > 0; o >>= 1) r += __shfl_down_sync(0xFFFFFFFFu, r, o);
        if (threadIdx.x == 0) g_bsum[blockIdx.x] = r;
    }
}

// per-block: reduce preceding block sums -> offset; local exclusive scan; write
__global__ void __launch_bounds__(1024) k_scan_apply() {
    __shared__ int red[32];
    __shared__ int s_boff;
    __shared__ int wsum[32];
    const int t = threadIdx.x;
    const int lane = t & 31, warp = t >> 5;
    const int b = blockIdx.x;

    int local = (t < b) ? g_bsum[t] : 0;
#pragma unroll
    for (int o = 16; o > 0; o >>= 1) local += __shfl_down_sync(0xFFFFFFFFu, local, o);
    if (lane == 0) red[warp] = local;
    __syncthreads();
    if (t < 32) {
        int r = red[t];
#pragma unroll
        for (int o = 16; o > 0; o >>= 1) r += __shfl_down_sync(0xFFFFFFFFu, r, o);
        if (t == 0) s_boff = r;
    }
    __syncthreads();
    const int boff = s_boff;

    int i = b * 1024 + t;
    int v = (i < NSEG) ? g_deg[i] : 0;
    int x = v;
#pragma unroll
    for (int o = 1; o < 32; o <<= 1) {
        int y = __shfl_up_sync(0xFFFFFFFFu, x, o);
        if (lane >= o) x += y;
    }
    if (lane == 31) wsum[warp] = x;
    __syncthreads();
    if (t < 32) {
        int y = wsum[t];
        int z = y;
#pragma unroll
        for (int o = 1; o < 32; o <<= 1) {
            int q = __shfl_up_sync(0xFFFFFFFFu, z, o);
            if (t >= o) z += q;
        }
        wsum[t] = z - y;
    }
    __syncthreads();
    if (i < NSEG) {
        int o = x - v + wsum[warp] + boff;
        g_offs[i] = o;
        g_cursor[i] = o;
    }
    if (b == 0 && t == 0) g_offs[NSEG] = EE;
}

__global__ void k_fill(const int* __restrict__ src, const int* __restrict__ dst,
                       const int* __restrict__ typ) {
    int t = blockIdx.x * blockDim.x + threadIdx.x;
    if (t >= EE / 4) return;
    int4 s = *(const int4*)(src + 4 * t);
    int4 d = *(const int4*)(dst + 4 * t);
    int4 y = *(const int4*)(typ + 4 * t);
    int p0 = atomicAdd(&g_cursor[d.x * RR + y.x], 1);
    int p1 = atomicAdd(&g_cursor[d.y * RR + y.y], 1);
    int p2 = atomicAdd(&g_cursor[d.z * RR + y.z], 1);
    int p3 = atomicAdd(&g_cursor[d.w * RR + y.w], 1);
    g_eidx[p0] = s.x;
    g_eidx[p1] = s.y;
    g_eidx[p2] = s.z;
    g_eidx[p3] = s.w;
}

// ---------------- aggregation: 2 warps per node, 4 relations each --------------
__global__ void __launch_bounds__(256) k_aggregate_h(const __half* __restrict__ feat) {
    int w = (blockIdx.x * blockDim.x + threadIdx.x) >> 5;
    int lane = threadIdx.x & 31;
    if (w >= NN * 2) return;
    const int node = w >> 1;
    const int rbase = (w & 1) * 4;                 // relations [rbase, rbase+4)
    __half* zrow = g_Z + (size_t)node * KRED + rbase * DH;
    const int co = lane * 4;   // 4 halves per lane

    const int base = node * RR + rbase;            // base % 4 == 0 -> 16B aligned
    int4 oA = *(const int4*)(g_offs + base);
    int o4 = g_offs[base + 4];
    int offs[5] = {oA.x, oA.y, oA.z, oA.w, o4};

#pragma unroll
    for (int r = 0; r < 4; r++) {
        int s = offs[r];
        int e = offs[r + 1];
        float4 acc0 = make_float4(0.f, 0.f, 0.f, 0.f);
        float4 acc1 = make_float4(0.f, 0.f, 0.f, 0.f);
        int i = s;
        for (; i + 4 <= e; i += 4) {
            uint2 u0 = *(const uint2*)(feat + (size_t)g_eidx[i] * DH + co);
            uint2 u1 = *(const uint2*)(feat + (size_t)g_eidx[i + 1] * DH + co);
            uint2 u2 = *(const uint2*)(feat + (size_t)g_eidx[i + 2] * DH + co);
            uint2 u3 = *(const uint2*)(feat + (size_t)g_eidx[i + 3] * DH + co);
            float2 a0 = __half22float2(*(__half2*)&u0.x);
            float2 b0 = __half22float2(*(__half2*)&u0.y);
            float2 a1 = __half22float2(*(__half2*)&u1.x);
            float2 b1 = __half22float2(*(__half2*)&u1.y);
            float2 a2 = __half22float2(*(__half2*)&u2.x);
            float2 b2 = __half22float2(*(__half2*)&u2.y);
            float2 a3 = __half22float2(*(__half2*)&u3.x);
            float2 b3 = __half22float2(*(__half2*)&u3.y);
            acc0.x += a0.x + a1.x; acc0.y += a0.y + a1.y;
            acc0.z += b0.x + b1.x; acc0.w += b0.y + b1.y;
            acc1.x += a2.x + a3.x; acc1.y += a2.y + a3.y;
            acc1.z += b2.x + b3.x; acc1.w += b2.y + b3.y;
        }
        for (; i < e; i++) {
            uint2 u0 = *(const uint2*)(feat + (size_t)g_eidx[i] * DH + co);
            float2 a = __half22float2(*(__half2*)&u0.x);
            float2 b = __half22float2(*(__half2*)&u0.y);
            acc0.x += a.x; acc0.y += a.y; acc0.z += b.x; acc0.w += b.y;
        }
        float inv = (e > s) ? 1.f / (float)(e - s) : 0.f;
        float2 m0 = make_float2((acc0.x + acc1.x) * inv, (acc0.y + acc1.y) * inv);
        float2 m1 = make_float2((acc0.z + acc1.z) * inv, (acc0.w + acc1.w) * inv);
        __half2 h0 = __float22half2_rn(m0);
        __half2 h1 = __float22half2_rn(m1);
        uint2 u;
        u.x = *(uint32_t*)&h0;
        u.y = *(uint32_t*)&h1;
        *(uint2*)(zrow + r * DH + co) = u;
    }
}

// ---------------- fp16 mma GEMM + fused epilogue (paired B, R13 pipeline) ------
// A chunks 0..15 from Z (KRED stride); chunks 16,17 = self features from feat.
// mode 0: C16 = relu(...); mode 1: pool into g_gsum.
__global__ void __launch_bounds__(256, 2)
k_gemm_h(const __half* __restrict__ A, const __half* __restrict__ feat,
         const __half* __restrict__ Bi, const float* __restrict__ bias,
         __half* __restrict__ C16, const int* __restrict__ batch, int M, int mode) {
    extern __shared__ __align__(16) char smem[];
    const uint32_t smem_u32 = smem_to_u32(smem);
    const int tid = threadIdx.x;
    const int wid = tid >> 5, lane = tid & 31;
    const int warp_m = wid & 3, warp_n = wid >> 2;
    const int g = lane >> 2, tig = lane & 3;
    const int bm = blockIdx.x * BM;

    const uint32_t aOff[2] = {0u, (uint32_t)(A_TILE_B + B_TILE_B)};
    const uint32_t bOff[2] = {(uint32_t)A_TILE_B,
                              (uint32_t)(2 * A_TILE_B + B_TILE_B)};

    float acc[2][8][4];
#pragma unroll
    for (int i = 0; i < 2; i++)
#pragma unroll
        for (int j = 0; j < 8; j++)
#pragma unroll
            for (int q = 0; q < 4; q++) acc[i][j][q] = 0.f;

    auto load_tile = [&](int c, int buf) {
        // A: 128 rows x 64 halves (128 B/row) -> 1024 16B chunks
#pragma unroll
        for (int it = 0; it < 4; it++) {
            int idx = tid + it * 256;          // 0..1023
            int row = idx >> 3;
            int q = idx & 7;
            int gm = bm + row;
            uint32_t d = smem_u32 + aOff[buf] + row * (A_PADH * 2) + q * 16;
            const __half* srcp = (c < 16)
                ? A + (size_t)gm * KRED + c * BK + q * 8
                : feat + (size_t)gm * DH + (c - 16) * BK + q * 8;
            cp_async16(d, srcp, (gm < M) ? 16u : 0u);
        }
        // B: paired layout chunk = 16384 B = 1024 16B chunks (exact 4 iters)
        const __half* Bb = Bi + (size_t)c * 8192;
#pragma unroll
        for (int it = 0; it < 4; it++) {
            int idx = tid + it * 256;
            cp_async16(smem_u32 + bOff[buf] + idx * 16, Bb + idx * 8, 16u);
        }
    };

    load_tile(0, 0);
    CP_COMMIT();

    const int mbase = warp_m * 32;
    const int nbase = warp_n * 64;

    for (int c = 0; c < NCHUNK; c++) {
        const int buf = c & 1;
        if (c + 1 < NCHUNK) {
            load_tile(c + 1, buf ^ 1);
            CP_COMMIT();
            CP_WAIT(1);
        } else {
            CP_WAIT(0);
        }
        __syncthreads();

        const uint32_t* As = (const uint32_t*)(smem + aOff[buf]);   // row stride 36 words
        const uint2* Bs2 = (const uint2*)(smem + bOff[buf]);        // [s][n][tig] pairs

#pragma unroll
        for (int s = 0; s < 4; s++) {           // four k16 steps per BK=64
            const int kw = s * 8;
            uint32_t a[2][4];
#pragma unroll
            for (int mt = 0; mt < 2; mt++) {
                int r0 = mbase + mt * 16 + g;
                a[mt][0] = As[r0 * 36 + kw + tig];
                a[mt][1] = As[(r0 + 8) * 36 + kw + tig];
                a[mt][2] = As[r0 * 36 + kw + tig + 4];
                a[mt][3] = As[(r0 + 8) * 36 + kw + tig + 4];
            }
#pragma unroll
            for (int nt = 0; nt < 8; nt++) {
                int n = nbase + nt * 8 + g;
                uint2 bb = Bs2[s * 512 + n * 4 + tig];
                mma_f16(acc[0][nt], a[0], bb.x, bb.y);
                mma_f16(acc[1][nt], a[1], bb.x, bb.y);
            }
        }
        __syncthreads();
    }

    // ---- epilogue ----
    if (mode == 0) {
#pragma unroll
        for (int nt = 0; nt < 8; nt++) {
            int col = nbase + nt * 8 + tig * 2;
            float b0 = __ldg(bias + col);
            float b1 = __ldg(bias + col + 1);
#pragma unroll
            for (int mt = 0; mt < 2; mt++) {
#pragma unroll
                for (int h = 0; h < 2; h++) {
                    int gm = bm + mbase + mt * 16 + g + h * 8;
                    if (gm >= M) continue;
                    float v0 = fmaxf(acc[mt][nt][2 * h + 0] + b0, 0.f);
                    float v1 = fmaxf(acc[mt][nt][2 * h + 1] + b1, 0.f);
                    __half2 hh = __float22half2_rn(make_float2(v0, v1));
                    *(__half2*)(C16 + (size_t)gm * DH + col) = hh;
                }
            }
        }
    } else {
        int rows[4], grs[4];
        bool ok[4];
#pragma unroll
        for (int q = 0; q < 4; q++) {
            rows[q] = bm + mbase + (q >> 1) * 16 + g + (q & 1) * 8;
            ok[q] = rows[q] < M;
            grs[q] = ok[q] ? __ldg(batch + rows[q]) : -1;
        }
        bool same = ok[0] & ok[1] & ok[2] & ok[3] &
                    (grs[0] == grs[1]) & (grs[0] == grs[2]) & (grs[0] == grs[3]);
#pragma unroll
        for (int nt = 0; nt < 8; nt++) {
            int col = nbase + nt * 8 + tig * 2;
            float b0 = __ldg(bias + col);
            float b1 = __ldg(bias + col + 1);
            if (same) {
                float s0 = 0.f, s1 = 0.f;
#pragma unroll
                for (int q = 0; q < 4; q++) {
                    int mt = q >> 1, h = q & 1;
                    s0 += fmaxf(acc[mt][nt][2 * h + 0] + b0, 0.f);
                    s1 += fmaxf(acc[mt][nt][2 * h + 1] + b1, 0.f);
                }
                atomicAdd(&g_gsum[grs[0] * DH + col], s0);
                atomicAdd(&g_gsum[grs[0] * DH + col + 1], s1);
            } else {
#pragma unroll
                for (int q = 0; q < 4; q++) {
                    if (!ok[q]) continue;
                    int mt = q >> 1, h = q & 1;
                    float v0 = fmaxf(acc[mt][nt][2 * h + 0] + b0, 0.f);
                    float v1 = fmaxf(acc[mt][nt][2 * h + 1] + b1, 0.f);
                    atomicAdd(&g_gsum[grs[q] * DH + col], v0);
                    atomicAdd(&g_gsum[grs[q] * DH + col + 1], v1);
                }
            }
        }
    }
}

// ---------------- final linear: one block per graph ----------------------------
__global__ void __launch_bounds__(128) k_final(const float* __restrict__ lw,
                                               const float* __restrict__ lb,
                                               float* __restrict__ out) {
    __shared__ float row[DH];
    __shared__ float cls[NCLS][4];
    const int g = blockIdx.x;
    const int t = threadIdx.x;
    const float inv = 1.f / fmaxf((float)g_gcnt[g], 1.f);
    row[t] = g_gsum[g * DH + t] * inv;
    __syncthreads();

    if (t < NCLS * 4) {
        int c = t >> 2, part = t & 3;
        float s = 0.f;
#pragma unroll
        for (int d = part * 32; d < part * 32 + 32; d++)
            s += row[d] * __ldg(lw + d * NCLS + c);
        cls[c][part] = s;
    }
    __syncthreads();
    if (t < NCLS)
        out[g * NCLS + t] = cls[t][0] + cls[t][1] + cls[t][2] + cls[t][3] + __ldg(lb + t);
}

// ---------------- launch ----------------
extern "C" void kernel_launch(void* const* d_in, const int* in_sizes, int n_in,
                              void* d_out, int out_size) {
    const float* x     = (const float*)d_in[0];
    const int*   ei    = (const int*)d_in[1];     // [2,E]
    const int*   etype = (const int*)d_in[2];
    const int*   batch = (const int*)d_in[3];
    const float* W1    = (const float*)d_in[4];
    const float* root1 = (const float*)d_in[5];
    const float* b1    = (const float*)d_in[6];
    const float* W2    = (const float*)d_in[7];
    const float* root2 = (const float*)d_in[8];
    const float* b2    = (const float*)d_in[9];
    const float* lw    = (const float*)d_in[10];
    const float* lb    = (const float*)d_in[11];
    float* out = (float*)d_out;

    const int* src = ei;
    const int* dst = ei + EE;

    __half *Z, *X16, *H16, *W1i, *W2i;
    cudaGetSymbolAddress((void**)&Z,   g_Z);
    cudaGetSymbolAddress((void**)&X16, g_X16);
    cudaGetSymbolAddress((void**)&H16, g_H16);
    cudaGetSymbolAddress((void**)&W1i, g_W1i);
    cudaGetSymbolAddress((void**)&W2i, g_W2i);

    cudaFuncSetAttribute(k_gemm_h, cudaFuncAttributeMaxDynamicSharedMemorySize,
                         SMEM_GEMM_BYTES);

    const int TB = 256;
    const int scanBlocks = (NSEG + 1023) / 1024;    // 391

    // prep (zero/convert/paired weight interleave)
    k_prep<<<(NN * 32 + TB - 1) / TB, TB>>>(x, W1, root1, W2, root2);
    // CSR build (4 edges/thread)
    k_count<<<(EE / 4 + TB - 1) / TB, TB>>>(dst, etype, batch);
    k_scan_sums<<<scanBlocks, 1024>>>();
    k_scan_apply<<<scanBlocks, 1024>>>();
    k_fill<<<(EE / 4 + TB - 1) / TB, TB>>>(src, dst, etype);

    const int aggBlocks = (NN * 2 * 32 + TB - 1) / TB;   // 2 warps per node
    const int gemmBlocks = (NN + BM - 1) / BM;           // 391

    // layer 1
    k_aggregate_h<<<aggBlocks, TB>>>(X16);
    k_gemm_h<<<gemmBlocks, TB, SMEM_GEMM_BYTES>>>(Z, X16, W1i, b1, H16, batch, NN, 0);
    // layer 2 (fused pool epilogue)
    k_aggregate_h<<<aggBlocks, TB>>>(H16);
    k_gemm_h<<<gemmBlocks, TB, SMEM_GEMM_BYTES>>>(Z, H16, W2i, b2, nullptr, batch, NN, 1);

    // classify
    k_final<<<GG, 128>>>(lw, lb, out);
}

// round 17
// speedup vs baseline: 1.1389x; 1.0075x over previous
#include <cuda_runtime.h>
#include <cuda_fp16.h>
#include <cstdint>

// ---------------- problem constants ----------------
#define NN    50000
#define EE    1600000
#define RR    8
#define NSEG  (NN*RR)        // 400000
#define DH    128
#define KDIM  1152           // 8*128 relation blocks + 128 root (self) block
#define KRED  1024           // relation blocks only (self read direct from feat)
#define GG    64
#define NCLS  10

#define BM    128
#define BK    64
#define NCHUNK (KDIM/BK)     // 18  (chunks 16,17 = self block from feat)

// fp16 smem tiles
#define A_PADH 72                         // halves per A row (144 B)
#define A_TILE_B (BM * A_PADH * 2)        // 18432
// B paired layout: per chunk: [s:4][n:128][tig:4][h:2] halves = 8192 halves = 16 KB
#define B_TILE_B 16384
#define SMEM_GEMM_BYTES (2 * (A_TILE_B + B_TILE_B))   // 69632

#define WELEMS2 (NCHUNK * 8192)           // 147456 halves per weight matrix

// ---------------- device scratch ----------------
__device__ int    g_deg[NSEG];
__device__ __align__(16) int g_offs[NSEG + 4];   // 16B-aligned for int4 loads
__device__ int    g_cursor[NSEG];
__device__ int    g_bsum[512];
__device__ int    g_eidx[EE];
__device__ __half g_Z[(size_t)NN * KRED];        // 102.4 MB
__device__ __half g_X16[(size_t)NN * DH];
__device__ __half g_H16[(size_t)NN * DH];
__device__ __half g_W1i[WELEMS2];
__device__ __half g_W2i[WELEMS2];
__device__ float  g_gsum[GG * DH];
__device__ int    g_gcnt[GG];

// ---------------- helpers ----------------
__device__ __forceinline__ uint32_t smem_to_u32(const void* p) {
    uint32_t a;
    asm("{ .reg .u64 t; cvta.to.shared.u64 t, %1; cvt.u32.u64 %0, t; }" : "=r"(a) : "l"(p));
    return a;
}
__device__ __forceinline__ void cp_async16(uint32_t dst, const void* src, uint32_t src_sz) {
    asm volatile("cp.async.cg.shared.global [%0], [%1], 16, %2;"
                 :: "r"(dst), "l"(src), "r"(src_sz));
}
#define CP_COMMIT() asm volatile("cp.async.commit_group;" ::: "memory")
#define CP_WAIT(n)  asm volatile("cp.async.wait_group %0;" :: "n"(n) : "memory")

__device__ __forceinline__ void mma_f16(float* c, const uint32_t* a,
                                        uint32_t b0, uint32_t b1) {
    asm volatile(
        "mma.sync.aligned.m16n8k16.row.col.f32.f16.f16.f32 "
        "{%0,%1,%2,%3}, {%4,%5,%6,%7}, {%8,%9}, {%0,%1,%2,%3};"
        : "+f"(c[0]), "+f"(c[1]), "+f"(c[2]), "+f"(c[3])
        : "r"(a[0]), "r"(a[1]), "r"(a[2]), "r"(a[3]), "r"(b0), "r"(b1));
}

// ---------------- prep: zero + paired weight interleave + x->fp16 -------------
__global__ void __launch_bounds__(256) k_prep(const float* __restrict__ x,
                                              const float* __restrict__ W1,
                                              const float* __restrict__ root1,
                                              const float* __restrict__ W2,
                                              const float* __restrict__ root2) {
    int i = blockIdx.x * blockDim.x + threadIdx.x;       // up to NN*32 = 1.6M
    if (i < NSEG)    g_deg[i] = 0;
    if (i < GG * DH) g_gsum[i] = 0.f;
    if (i < GG)      g_gcnt[i] = 0;
    if (i < WELEMS2) {
        int w = i >> 1, par = i & 1;
        int c = w >> 12;            // /4096
        int rem = w & 4095;
        int s = rem >> 10;
        int r2 = rem & 1023;
        int n = r2 >> 3;
        int q = r2 & 7;
        int tig = q >> 1, h = q & 1;
        int kp = c * 32 + s * 8 + tig + h * 4;
        int k = 2 * kp + par;
        float v1, v2;
        if (k < RR * DH) {
            v1 = W1[(size_t)k * DH + n];
            v2 = W2[(size_t)k * DH + n];
        } else {
            v1 = root1[(size_t)(k - RR * DH) * DH + n];
            v2 = root2[(size_t)(k - RR * DH) * DH + n];
        }
        g_W1i[i] = __float2half(v1);
        g_W2i[i] = __float2half(v2);
    }
    if (i < NN * 32) {
        float4 v = *(const float4*)(x + (size_t)i * 4);
        __half2 h0 = __float22half2_rn(make_float2(v.x, v.y));
        __half2 h1 = __float22half2_rn(make_float2(v.z, v.w));
        uint2 u;
        u.x = *(uint32_t*)&h0;
        u.y = *(uint32_t*)&h1;
        *(uint2*)(g_X16 + (size_t)i * 4) = u;
    }
}

// ---------------- CSR build: 4 edges/thread -----------------------------------
__global__ void k_count(const int* __restrict__ dst, const int* __restrict__ typ,
                        const int* __restrict__ batch) {
    int t = blockIdx.x * blockDim.x + threadIdx.x;
    if (t < EE / 4) {
        int4 d = *(const int4*)(dst + 4 * t);
        int4 y = *(const int4*)(typ + 4 * t);
        atomicAdd(&g_deg[d.x * RR + y.x], 1);
        atomicAdd(&g_deg[d.y * RR + y.y], 1);
        atomicAdd(&g_deg[d.z * RR + y.z], 1);
        atomicAdd(&g_deg[d.w * RR + y.w], 1);
    }
    if (t < NN) atomicAdd(&g_gcnt[batch[t]], 1);
}

// block sums over 1024-element tiles of g_deg
__global__ void __launch_bounds__(1024) k_scan_sums() {
    __shared__ int red[32];
    int i = blockIdx.x * 1024 + threadIdx.x;
    int lane = threadIdx.x & 31, warp = threadIdx.x >> 5;
    int v = (i < NSEG) ? g_deg[i] : 0;
    int s = v;
#pragma unroll
    for (int o = 16; o > 0; o >>= 1) s += __shfl_down_sync(0xFFFFFFFFu, s, o);
    if (lane == 0) red[warp] = s;
    __syncthreads();
    if (threadIdx.x < 32) {
        int r = red[threadIdx.x];
#pragma unroll
        for (int o = 16; o > 0; o >>= 1) r += __shfl_down_sync(0xFFFFFFFFu, r, o);
        if (threadIdx.x == 0) g_bsum[blockIdx.x] = r;
    }
}

// per-block: reduce preceding block sums -> offset; local exclusive scan; write
__global__ void __launch_bounds__(1024) k_scan_apply() {
    __shared__ int red[32];
    __shared__ int s_boff;
    __shared__ int wsum[32];
    const int t = threadIdx.x;
    const int lane = t & 31, warp = t >> 5;
    const int b = blockIdx.x;

    int local = (t < b) ? g_bsum[t] : 0;
#pragma unroll
    for (int o = 16; o > 0; o >>= 1) local += __shfl_down_sync(0xFFFFFFFFu, local, o);
    if (lane == 0) red[warp] = local;
    __syncthreads();
    if (t < 32) {
        int r = red[t];
#pragma unroll
        for (int o = 16; o > 0; o >>= 1) r += __shfl_down_sync(0xFFFFFFFFu, r, o);
        if (t == 0) s_boff = r;
    }
    __syncthreads();
    const int boff = s_boff;

    int i = b * 1024 + t;
    int v = (i < NSEG) ? g_deg[i] : 0;
    int x = v;
#pragma unroll
    for (int o = 1; o < 32; o <<= 1) {
        int y = __shfl_up_sync(0xFFFFFFFFu, x, o);
        if (lane >= o) x += y;
    }
    if (lane == 31) wsum[warp] = x;
    __syncthreads();
    if (t < 32) {
        int y = wsum[t];
        int z = y;
#pragma unroll
        for (int o = 1; o < 32; o <<= 1) {
            int q = __shfl_up_sync(0xFFFFFFFFu, z, o);
            if (t >= o) z += q;
        }
        wsum[t] = z - y;
    }
    __syncthreads();
    if (i < NSEG) {
        int o = x - v + wsum[warp] + boff;
        g_offs[i] = o;
        g_cursor[i] = o;
    }
    if (b == 0 && t == 0) g_offs[NSEG] = EE;
}

__global__ void k_fill(const int* __restrict__ src, const int* __restrict__ dst,
                       const int* __restrict__ typ) {
    int t = blockIdx.x * blockDim.x + threadIdx.x;
    if (t >= EE / 4) return;
    int4 s = *(const int4*)(src + 4 * t);
    int4 d = *(const int4*)(dst + 4 * t);
    int4 y = *(const int4*)(typ + 4 * t);
    int p0 = atomicAdd(&g_cursor[d.x * RR + y.x], 1);
    int p1 = atomicAdd(&g_cursor[d.y * RR + y.y], 1);
    int p2 = atomicAdd(&g_cursor[d.z * RR + y.z], 1);
    int p3 = atomicAdd(&g_cursor[d.w * RR + y.w], 1);
    g_eidx[p0] = s.x;
    g_eidx[p1] = s.y;
    g_eidx[p2] = s.z;
    g_eidx[p3] = s.w;
}

// ---------------- aggregation: 2 warps per node, 4 relations each --------------
__global__ void __launch_bounds__(256) k_aggregate_h(const __half* __restrict__ feat) {
    int w = (blockIdx.x * blockDim.x + threadIdx.x) >> 5;
    int lane = threadIdx.x & 31;
    if (w >= NN * 2) return;
    const int node = w >> 1;
    const int rbase = (w & 1) * 4;                 // relations [rbase, rbase+4)
    __half* zrow = g_Z + (size_t)node * KRED + rbase * DH;
    const int co = lane * 4;   // 4 halves per lane

    const int base = node * RR + rbase;            // base % 4 == 0 -> 16B aligned
    int4 oA = *(const int4*)(g_offs + base);
    int o4 = g_offs[base + 4];
    int offs[5] = {oA.x, oA.y, oA.z, oA.w, o4};

#pragma unroll
    for (int r = 0; r < 4; r++) {
        int s = offs[r];
        int e = offs[r + 1];
        float4 acc0 = make_float4(0.f, 0.f, 0.f, 0.f);
        float4 acc1 = make_float4(0.f, 0.f, 0.f, 0.f);
        int i = s;
        for (; i + 4 <= e; i += 4) {
            uint2 u0 = *(const uint2*)(feat + (size_t)g_eidx[i] * DH + co);
            uint2 u1 = *(const uint2*)(feat + (size_t)g_eidx[i + 1] * DH + co);
            uint2 u2 = *(const uint2*)(feat + (size_t)g_eidx[i + 2] * DH + co);
            uint2 u3 = *(const uint2*)(feat + (size_t)g_eidx[i + 3] * DH + co);
            float2 a0 = __half22float2(*(__half2*)&u0.x);
            float2 b0 = __half22float2(*(__half2*)&u0.y);
            float2 a1 = __half22float2(*(__half2*)&u1.x);
            float2 b1 = __half22float2(*(__half2*)&u1.y);
            float2 a2 = __half22float2(*(__half2*)&u2.x);
            float2 b2 = __half22float2(*(__half2*)&u2.y);
            float2 a3 = __half22float2(*(__half2*)&u3.x);
            float2 b3 = __half22float2(*(__half2*)&u3.y);
            acc0.x += a0.x + a1.x; acc0.y += a0.y + a1.y;
            acc0.z += b0.x + b1.x; acc0.w += b0.y + b1.y;
            acc1.x += a2.x + a3.x; acc1.y += a2.y + a3.y;
            acc1.z += b2.x + b3.x; acc1.w += b2.y + b3.y;
        }
        for (; i < e; i++) {
            uint2 u0 = *(const uint2*)(feat + (size_t)g_eidx[i] * DH + co);
            float2 a = __half22float2(*(__half2*)&u0.x);
            float2 b = __half22float2(*(__half2*)&u0.y);
            acc0.x += a.x; acc0.y += a.y; acc0.z += b.x; acc0.w += b.y;
        }
        float inv = (e > s) ? 1.f / (float)(e - s) : 0.f;
        float2 m0 = make_float2((acc0.x + acc1.x) * inv, (acc0.y + acc1.y) * inv);
        float2 m1 = make_float2((acc0.z + acc1.z) * inv, (acc0.w + acc1.w) * inv);
        __half2 h0 = __float22half2_rn(m0);
        __half2 h1 = __float22half2_rn(m1);
        uint2 u;
        u.x = *(uint32_t*)&h0;
        u.y = *(uint32_t*)&h1;
        *(uint2*)(zrow + r * DH + co) = u;
    }
}

// ---------------- fp16 mma GEMM, 512 threads, warp tile 32x32 ------------------
// 16 warps as 4(m) x 4(n); A chunks 0..15 from Z; chunks 16,17 self from feat.
// mode 0: C16 = relu(...); mode 1: pool into g_gsum.
__global__ void __launch_bounds__(512, 2)
k_gemm_h(const __half* __restrict__ A, const __half* __restrict__ feat,
         const __half* __restrict__ Bi, const float* __restrict__ bias,
         __half* __restrict__ C16, const int* __restrict__ batch, int M, int mode) {
    extern __shared__ __align__(16) char smem[];
    const uint32_t smem_u32 = smem_to_u32(smem);
    const int tid = threadIdx.x;
    const int wid = tid >> 5, lane = tid & 31;
    const int warp_m = wid & 3, warp_n = wid >> 2;   // 4 x 4
    const int g = lane >> 2, tig = lane & 3;
    const int bm = blockIdx.x * BM;

    const uint32_t aOff[2] = {0u, (uint32_t)(A_TILE_B + B_TILE_B)};
    const uint32_t bOff[2] = {(uint32_t)A_TILE_B,
                              (uint32_t)(2 * A_TILE_B + B_TILE_B)};

    float acc[2][4][4];
#pragma unroll
    for (int i = 0; i < 2; i++)
#pragma unroll
        for (int j = 0; j < 4; j++)
#pragma unroll
            for (int q = 0; q < 4; q++) acc[i][j][q] = 0.f;

    auto load_tile = [&](int c, int buf) {
        // A: 128 rows x 64 halves (128 B/row) -> 1024 16B chunks, 512 threads x 2
#pragma unroll
        for (int it = 0; it < 2; it++) {
            int idx = tid + it * 512;          // 0..1023
            int row = idx >> 3;
            int q = idx & 7;
            int gm = bm + row;
            uint32_t d = smem_u32 + aOff[buf] + row * (A_PADH * 2) + q * 16;
            const __half* srcp = (c < 16)
                ? A + (size_t)gm * KRED + c * BK + q * 8
                : feat + (size_t)gm * DH + (c - 16) * BK + q * 8;
            cp_async16(d, srcp, (gm < M) ? 16u : 0u);
        }
        // B: paired layout chunk = 16384 B = 1024 16B chunks
        const __half* Bb = Bi + (size_t)c * 8192;
#pragma unroll
        for (int it = 0; it < 2; it++) {
            int idx = tid + it * 512;
            cp_async16(smem_u32 + bOff[buf] + idx * 16, Bb + idx * 8, 16u);
        }
    };

    load_tile(0, 0);
    CP_COMMIT();

    const int mbase = warp_m * 32;
    const int nbase = warp_n * 32;

    for (int c = 0; c < NCHUNK; c++) {
        const int buf = c & 1;
        if (c + 1 < NCHUNK) {
            load_tile(c + 1, buf ^ 1);
            CP_COMMIT();
            CP_WAIT(1);
        } else {
            CP_WAIT(0);
        }
        __syncthreads();

        const uint32_t* As = (const uint32_t*)(smem + aOff[buf]);   // row stride 36 words
        const uint2* Bs2 = (const uint2*)(smem + bOff[buf]);        // [s][n][tig] pairs

#pragma unroll
        for (int s = 0; s < 4; s++) {           // four k16 steps per BK=64
            const int kw = s * 8;
            uint32_t a[2][4];
#pragma unroll
            for (int mt = 0; mt < 2; mt++) {
                int r0 = mbase + mt * 16 + g;
                a[mt][0] = As[r0 * 36 + kw + tig];
                a[mt][1] = As[(r0 + 8) * 36 + kw + tig];
                a[mt][2] = As[r0 * 36 + kw + tig + 4];
                a[mt][3] = As[(r0 + 8) * 36 + kw + tig + 4];
            }
#pragma unroll
            for (int nt = 0; nt < 4; nt++) {
                int n = nbase + nt * 8 + g;
                uint2 bb = Bs2[s * 512 + n * 4 + tig];
                mma_f16(acc[0][nt], a[0], bb.x, bb.y);
                mma_f16(acc[1][nt], a[1], bb.x, bb.y);
            }
        }
        __syncthreads();
    }

    // ---- epilogue ----
    if (mode == 0) {
#pragma unroll
        for (int nt = 0; nt < 4; nt++) {
            int col = nbase + nt * 8 + tig * 2;
            float b0 = __ldg(bias + col);
            float b1 = __ldg(bias + col + 1);
#pragma unroll
            for (int mt = 0; mt < 2; mt++) {
#pragma unroll
                for (int h = 0; h < 2; h++) {
                    int gm = bm + mbase + mt * 16 + g + h * 8;
                    if (gm >= M) continue;
                    float v0 = fmaxf(acc[mt][nt][2 * h + 0] + b0, 0.f);
                    float v1 = fmaxf(acc[mt][nt][2 * h + 1] + b1, 0.f);
                    __half2 hh = __float22half2_rn(make_float2(v0, v1));
                    *(__half2*)(C16 + (size_t)gm * DH + col) = hh;
                }
            }
        }
    } else {
        int rows[4], grs[4];
        bool ok[4];
#pragma unroll
        for (int q = 0; q < 4; q++) {
            rows[q] = bm + mbase + (q >> 1) * 16 + g + (q & 1) * 8;
            ok[q] = rows[q] < M;
            grs[q] = ok[q] ? __ldg(batch + rows[q]) : -1;
        }
        bool same = ok[0] & ok[1] & ok[2] & ok[3] &
                    (grs[0] == grs[1]) & (grs[0] == grs[2]) & (grs[0] == grs[3]);
#pragma unroll
        for (int nt = 0; nt < 4; nt++) {
            int col = nbase + nt * 8 + tig * 2;
            float b0 = __ldg(bias + col);
            float b1 = __ldg(bias + col + 1);
            if (same) {
                float s0 = 0.f, s1 = 0.f;
#pragma unroll
                for (int q = 0; q < 4; q++) {
                    int mt = q >> 1, h = q & 1;
                    s0 += fmaxf(acc[mt][nt][2 * h + 0] + b0, 0.f);
                    s1 += fmaxf(acc[mt][nt][2 * h + 1] + b1, 0.f);
                }
                atomicAdd(&g_gsum[grs[0] * DH + col], s0);
                atomicAdd(&g_gsum[grs[0] * DH + col + 1], s1);
            } else {
#pragma unroll
                for (int q = 0; q < 4; q++) {
                    if (!ok[q]) continue;
                    int mt = q >> 1, h = q & 1;
                    float v0 = fmaxf(acc[mt][nt][2 * h + 0] + b0, 0.f);
                    float v1 = fmaxf(acc[mt][nt][2 * h + 1] + b1, 0.f);
                    atomicAdd(&g_gsum[grs[q] * DH + col], v0);
                    atomicAdd(&g_gsum[grs[q] * DH + col + 1], v1);
                }
            }
        }
    }
}

// ---------------- final linear: one block per graph ----------------------------
__global__ void __launch_bounds__(128) k_final(const float* __restrict__ lw,
                                               const float* __restrict__ lb,
                                               float* __restrict__ out) {
    __shared__ float row[DH];
    __shared__ float cls[NCLS][4];
    const int g = blockIdx.x;
    const int t = threadIdx.x;
    const float inv = 1.f / fmaxf((float)g_gcnt[g], 1.f);
    row[t] = g_gsum[g * DH + t] * inv;
    __syncthreads();

    if (t < NCLS * 4) {
        int c = t >> 2, part = t & 3;
        float s = 0.f;
#pragma unroll
        for (int d = part * 32; d < part * 32 + 32; d++)
            s += row[d] * __ldg(lw + d * NCLS + c);
        cls[c][part] = s;
    }
    __syncthreads();
    if (t < NCLS)
        out[g * NCLS + t] = cls[t][0] + cls[t][1] + cls[t][2] + cls[t][3] + __ldg(lb + t);
}

// ---------------- launch ----------------
extern "C" void kernel_launch(void* const* d_in, const int* in_sizes, int n_in,
                              void* d_out, int out_size) {
    const float* x     = (const float*)d_in[0];
    const int*   ei    = (const int*)d_in[1];     // [2,E]
    const int*   etype = (const int*)d_in[2];
    const int*   batch = (const int*)d_in[3];
    const float* W1    = (const float*)d_in[4];
    const float* root1 = (const float*)d_in[5];
    const float* b1    = (const float*)d_in[6];
    const float* W2    = (const float*)d_in[7];
    const float* root2 = (const float*)d_in[8];
    const float* b2    = (const float*)d_in[9];
    const float* lw    = (const float*)d_in[10];
    const float* lb    = (const float*)d_in[11];
    float* out = (float*)d_out;

    const int* src = ei;
    const int* dst = ei + EE;

    __half *Z, *X16, *H16, *W1i, *W2i;
    cudaGetSymbolAddress((void**)&Z,   g_Z);
    cudaGetSymbolAddress((void**)&X16, g_X16);
    cudaGetSymbolAddress((void**)&H16, g_H16);
    cudaGetSymbolAddress((void**)&W1i, g_W1i);
    cudaGetSymbolAddress((void**)&W2i, g_W2i);

    cudaFuncSetAttribute(k_gemm_h, cudaFuncAttributeMaxDynamicSharedMemorySize,
                         SMEM_GEMM_BYTES);

    const int TB = 256;
    const int scanBlocks = (NSEG + 1023) / 1024;    // 391

    // prep (zero/convert/paired weight interleave)
    k_prep<<<(NN * 32 + TB - 1) / TB, TB>>>(x, W1, root1, W2, root2);
    // CSR build (4 edges/thread)
    k_count<<<(EE / 4 + TB - 1) / TB, TB>>>(dst, etype, batch);
    k_scan_sums<<<scanBlocks, 1024>>>();
    k_scan_apply<<<scanBlocks, 1024>>>();
    k_fill<<<(EE / 4 + TB - 1) / TB, TB>>>(src, dst, etype);

    const int aggBlocks = (NN * 2 * 32 + TB - 1) / TB;   // 2 warps per node
    const int gemmBlocks = (NN + BM - 1) / BM;           // 391

    // layer 1
    k_aggregate_h<<<aggBlocks, TB>>>(X16);
    k_gemm_h<<<gemmBlocks, 512, SMEM_GEMM_BYTES>>>(Z, X16, W1i, b1, H16, batch, NN, 0);
    // layer 2 (fused pool epilogue)
    k_aggregate_h<<<aggBlocks, TB>>>(H16);
    k_gemm_h<<<gemmBlocks, 512, SMEM_GEMM_BYTES>>>(Z, H16, W2i, b2, nullptr, batch, NN, 1);

    // classify
    k_final<<<GG, 128>>>(lw, lb, out);
}